// round 11
// baseline (speedup 1.0000x reference)
#include <cuda_runtime.h>

#define GRID_N 32
#define CELLS  1024
#define SROW   24              // 2*SROW % 32 == 16 -> conflict-free
#define NROWS  34
#define NT     256
#define ESW    4

__global__ void __launch_bounds__(NT, 1)
dijkstra_grid_kernel(const float* __restrict__ wg, float* __restrict__ out)
{
    __shared__ float Ea[2][NROWS * SROW];   // even-x columns, per batch
    __shared__ float Oa[2][NROWS * SROW];   // odd-x columns, per batch
    __shared__ unsigned short pred [2][CELLS];
    __shared__ unsigned short pred2[2][CELLS];
    __shared__ unsigned short pred3[2][CELLS];
    __shared__ unsigned short pred4[2][CELLS];
    __shared__ unsigned char  mark[2][CELLS];
    __shared__ int flags[3];

    const int t  = threadIdx.x;
    const int tx = t & 15;
    const int ty = t >> 4;
    const float INF = __int_as_float(0x7f800000);

    const int x0 = tx * 2, y0 = ty * 2;
    const int rt = y0, ra = y0 + 1, rc = y0 + 2, rb = y0 + 3;
    const int b0 = blockIdx.x * 2;

    float wa[2], wb[2], wc[2], wd[2];
#pragma unroll
    for (int u = 0; u < 2; u++) {
        const float2* w2 = (const float2*)(wg + (size_t)(b0 + u) * CELLS);
        float2 wAB = w2[y0 * 16 + tx];
        float2 wCD = w2[(y0 + 1) * 16 + tx];
        wa[u] = wAB.x; wb[u] = wAB.y; wc[u] = wCD.x; wd[u] = wCD.y;
    }

    for (int i = t; i < 2 * NROWS * SROW; i += NT) {
        ((float*)Ea)[i] = INF; ((float*)Oa)[i] = INF;
    }
    for (int i = t; i < 2 * CELLS; i += NT) ((unsigned char*)mark)[i] = 0;
    if (t < 3) flags[t] = 0;
    __syncthreads();

    float a[2], bv[2], c[2], d[2];
#pragma unroll
    for (int u = 0; u < 2; u++) {
        a[u] = (t == 0) ? 0.0f : INF;
        bv[u] = INF; c[u] = INF; d[u] = INF;
        Ea[u][ra * SROW + tx] = a[u];  Oa[u][ra * SROW + tx + 1] = bv[u];
        Ea[u][rc * SROW + tx] = c[u];  Oa[u][rc * SROW + tx + 1] = d[u];
    }
    __syncthreads();

    // ---- chaotic min-plus relaxation, two independent batches interleaved
    // per thread (ILP=2 hides the FMIN chain latency). Per batch identical
    // to R7: 2x2 register Gauss-Seidel, Jacobi across blocks via smem.
    // Every candidate is d[nb] + w (RN): exact, monotone-decreasing,
    // reference-attainable path sums; unique fixed point == reference
    // Dijkstra distances bitwise. A converged batch keeps relaxing at its
    // fixed point (stable no-op) until both are done.
    int e = 0;
    for (;; e++) {
        float sa[2], sb[2], sc[2], sd[2];
#pragma unroll
        for (int u = 0; u < 2; u++) { sa[u]=a[u]; sb[u]=bv[u]; sc[u]=c[u]; sd[u]=d[u]; }

#pragma unroll
        for (int k = 0; k < ESW; k++) {
            float h[2][12];
            // front-batched: 24 conflict-free LDS across both batches
#pragma unroll
            for (int u = 0; u < 2; u++) {
                volatile float* E = Ea[u];
                volatile float* O = Oa[u];
                h[u][0]  = O[rt * SROW + tx];     h[u][1]  = E[rt * SROW + tx];
                h[u][2]  = O[rt * SROW + tx + 1]; h[u][3]  = E[rt * SROW + tx + 1];
                h[u][4]  = O[rb * SROW + tx];     h[u][5]  = E[rb * SROW + tx];
                h[u][6]  = O[rb * SROW + tx + 1]; h[u][7]  = E[rb * SROW + tx + 1];
                h[u][8]  = O[ra * SROW + tx];     h[u][9]  = O[rc * SROW + tx];
                h[u][10] = E[ra * SROW + tx + 1]; h[u][11] = E[rc * SROW + tx + 1];
            }
            // two independent 7-update GS chains (compiler interleaves)
#pragma unroll
            for (int u = 0; u < 2; u++) {
                const float tl = h[u][0], tce = h[u][1], tco = h[u][2], tre = h[u][3];
                const float bl = h[u][4], bce = h[u][5], bco = h[u][6], bre = h[u][7];
                const float l0 = h[u][8], l1  = h[u][9], r0  = h[u][10], r1 = h[u][11];

                a[u]  = fminf(a[u],  fminf(fminf(fminf(tl, tce), fminf(tco, l0)),
                                     fminf(fminf(bv[u], l1),  fminf(c[u], d[u]))) + wa[u]);
                bv[u] = fminf(bv[u], fminf(fminf(fminf(tce, tco), fminf(tre, a[u])),
                                     fminf(fminf(r0, c[u]),    fminf(d[u], r1))) + wb[u]);
                c[u]  = fminf(c[u],  fminf(fminf(fminf(l0, a[u]),   fminf(bv[u], l1)),
                                     fminf(fminf(d[u], bl),   fminf(bce, bco))) + wc[u]);
                d[u]  = fminf(d[u],  fminf(fminf(fminf(a[u], bv[u]),   fminf(r0, c[u])),
                                     fminf(fminf(r1, bce), fminf(bco, bre))) + wd[u]);
                c[u]  = fminf(c[u],  fminf(fminf(fminf(l0, a[u]),   fminf(bv[u], l1)),
                                     fminf(fminf(d[u], bl),   fminf(bce, bco))) + wc[u]);
                bv[u] = fminf(bv[u], fminf(fminf(fminf(tce, tco), fminf(tre, a[u])),
                                     fminf(fminf(r0, c[u]),    fminf(d[u], r1))) + wb[u]);
                a[u]  = fminf(a[u],  fminf(fminf(fminf(tl, tce), fminf(tco, l0)),
                                     fminf(fminf(bv[u], l1),  fminf(c[u], d[u]))) + wa[u]);

                volatile float* E = Ea[u];
                volatile float* O = Oa[u];
                E[ra * SROW + tx] = a[u];  O[ra * SROW + tx + 1] = bv[u];
                E[rc * SROW + tx] = c[u];  O[rc * SROW + tx + 1] = d[u];
            }
        }
        int ch = 0;
#pragma unroll
        for (int u = 0; u < 2; u++)
            ch |= (a[u] != sa[u]) | (bv[u] != sb[u]) | (c[u] != sc[u]) | (d[u] != sd[u]);
        if (ch) flags[e % 3] = 1;
        if (t == 0) flags[(e + 1) % 3] = 0;   // reset ordered by the barriers
        __syncthreads();
        if (!flags[e % 3]) break;             // uniform exit (both batches done)
    }

    // ---- predecessor = argmin over 8 neighbor distances (unique a.s.) ----
#pragma unroll
    for (int u = 0; u < 2; u++) {
        float tl  = Oa[u][rt * SROW + tx];
        float tce = Ea[u][rt * SROW + tx];
        float tco = Oa[u][rt * SROW + tx + 1];
        float tre = Ea[u][rt * SROW + tx + 1];
        float bl  = Oa[u][rb * SROW + tx];
        float bce = Ea[u][rb * SROW + tx];
        float bco = Oa[u][rb * SROW + tx + 1];
        float bre = Ea[u][rb * SROW + tx + 1];
        float l0  = Oa[u][ra * SROW + tx];
        float l1  = Oa[u][rc * SROW + tx];
        float r0  = Ea[u][ra * SROW + tx + 1];
        float r1  = Ea[u][rc * SROW + tx + 1];

        const int A = y0 * GRID_N + x0, B = A + 1, C = A + GRID_N, D = A + GRID_N + 1;

#define ARGMIN8(v1,i1,v2,i2,v3,i3,v4,i4,v5,i5,v6,i6,v7,i7,v8,i8, OUTCELL)      \
        {                                                                       \
            float bd = INF; int bi = 0;                                         \
            if (v1 < bd) { bd = v1; bi = i1; }                                  \
            if (v2 < bd) { bd = v2; bi = i2; }                                  \
            if (v3 < bd) { bd = v3; bi = i3; }                                  \
            if (v4 < bd) { bd = v4; bi = i4; }                                  \
            if (v5 < bd) { bd = v5; bi = i5; }                                  \
            if (v6 < bd) { bd = v6; bi = i6; }                                  \
            if (v7 < bd) { bd = v7; bi = i7; }                                  \
            if (v8 < bd) { bd = v8; bi = i8; }                                  \
            pred[u][OUTCELL] = (unsigned short)bi;                              \
        }

        ARGMIN8(tl, A-33, tce, A-32, tco, A-31, l0, A-1, bv[u], A+1,
                l1, A+31, c[u], A+32, d[u], A+33, A)
        ARGMIN8(tce, B-33, tco, B-32, tre, B-31, a[u], B-1, r0, B+1,
                c[u], B+31, d[u], B+32, r1, B+33, B)
        ARGMIN8(l0, C-33, a[u], C-32, bv[u], C-31, l1, C-1, d[u], C+1,
                bl, C+31, bce, C+32, bco, C+33, C)
        ARGMIN8(a[u], D-33, bv[u], D-32, r0, D-31, c[u], D-1, r1, D+1,
                bce, D+31, bco, D+32, bre, D+33, D)
#undef ARGMIN8
    }
    __syncthreads();

    // ---- skip pointers: pred2 = pred∘pred; pred3/pred4 ----
#pragma unroll
    for (int u = 0; u < 2; u++)
#pragma unroll
        for (int i = 0; i < 4; i++) {
            const int cell = t + i * NT;
            pred2[u][cell] = pred[u][pred[u][cell]];
        }
    __syncthreads();
#pragma unroll
    for (int u = 0; u < 2; u++)
#pragma unroll
        for (int i = 0; i < 4; i++) {
            const int cell = t + i * NT;
            const int q = pred2[u][cell];
            pred3[u][cell] = pred[u][q];
            pred4[u][cell] = pred2[u][q];
        }
    __syncthreads();

    // ---- parallel backtracks (lane 0 -> batch 0, lane 32 -> batch 1) ----
    // pred chain strictly decreases dist -> reaches cell 0.
    if (t == 0 || t == 32) {
        const int u = t >> 5;
        int cur = CELLS - 1;
        for (int i = 0; i < CELLS / 4 + 2; i++) {
            const int m1 = pred[u][cur];
            const int m2 = pred2[u][cur];
            const int m3 = pred3[u][cur];
            const int nx = pred4[u][cur];
            mark[u][cur] = 1;
            if (cur == 0) break;
            mark[u][m1] = 1;
            if (m1 == 0) break;
            mark[u][m2] = 1;
            if (m2 == 0) break;
            mark[u][m3] = 1;
            if (m3 == 0) break;
            cur = nx;
        }
    }
    __syncthreads();

    // ---- coalesced float2 output, both batches ----
#pragma unroll
    for (int u = 0; u < 2; u++) {
        float2* o2 = (float2*)(out + (size_t)(b0 + u) * CELLS);
        const int A = y0 * GRID_N + x0;
        o2[y0 * 16 + tx]       = make_float2(mark[u][A]      ? 1.0f : 0.0f,
                                             mark[u][A + 1]  ? 1.0f : 0.0f);
        o2[(y0 + 1) * 16 + tx] = make_float2(mark[u][A + 32] ? 1.0f : 0.0f,
                                             mark[u][A + 33] ? 1.0f : 0.0f);
    }
}

extern "C" void kernel_launch(void* const* d_in, const int* in_sizes, int n_in,
                              void* d_out, int out_size)
{
    const float* w = (const float*)d_in[0];
    float* out = (float*)d_out;
    int batches = in_sizes[0] / CELLS;     // 128 (even)
    dijkstra_grid_kernel<<<batches / 2, NT>>>(w, out);
}

// round 12
// speedup vs baseline: 1.2937x; 1.2937x over previous
#include <cuda_runtime.h>
#include <cstdint>

#define GRID_N 32
#define CELLS  1024
#define SP     18               // float2 pairs per padded row (16 + 2 halo)
#define NROWS  34               // 32 rows + halo
#define NT     256
#define ESW    4

__device__ __forceinline__ float2 lds2(uint32_t a) {
    float2 v;
    asm volatile("ld.volatile.shared.v2.f32 {%0,%1}, [%2];"
                 : "=f"(v.x), "=f"(v.y) : "r"(a));
    return v;
}
__device__ __forceinline__ void sts2(uint32_t a, float x, float y) {
    asm volatile("st.volatile.shared.v2.f32 [%0], {%1,%2};"
                 :: "r"(a), "f"(x), "f"(y) : "memory");
}

__global__ void __launch_bounds__(NT, 1)
dijkstra_grid_kernel(const float* __restrict__ wg, float* __restrict__ out)
{
    __shared__ float2 P[NROWS][SP];          // dist, x-pairs packed
    __shared__ unsigned short pred[CELLS], pred2[CELLS], pred3[CELLS], pred4[CELLS];
    __shared__ unsigned char  mark[CELLS];
    __shared__ int flags[3];

    const int b  = blockIdx.x;
    const int t  = threadIdx.x;
    const int tx = t & 15;
    const int ty = t >> 4;
    const float INF = __int_as_float(0x7f800000);

    const int x0 = tx * 2, y0 = ty * 2;
    const int rt = y0, ra = y0 + 1, rc = y0 + 2, rb = y0 + 3;  // padded rows

    const float2* w2 = (const float2*)(wg + (size_t)b * CELLS);
    const float2 wAB = w2[y0 * 16 + tx];
    const float2 wCD = w2[(y0 + 1) * 16 + tx];
    const float wa = wAB.x, wb = wAB.y, wc = wCD.x, wd = wCD.y;

    // smem byte addresses (loop-invariant)
    uint32_t pbase;
    asm("{ .reg .u64 tt; cvta.to.shared.u64 tt, %1; cvt.u32.u64 %0, tt; }"
        : "=r"(pbase) : "l"(P));
    const uint32_t aT = pbase + (uint32_t)(rt * SP + tx) * 8u;   // top halo pairs
    const uint32_t aB = pbase + (uint32_t)(rb * SP + tx) * 8u;   // bottom halo pairs
    const uint32_t aL = pbase + (uint32_t)(ra * SP + tx) * 8u;   // row A: left pair
    const uint32_t aC = pbase + (uint32_t)(rc * SP + tx) * 8u;   // row C: left pair
    const uint32_t sA = aL + 8u;                                  // own (a,b)
    const uint32_t sC = aC + 8u;                                  // own (c,d)

    // init dist = INF everywhere (incl. halos)
    {
        float* Pf = (float*)P;
        for (int i = t; i < NROWS * SP * 2; i += NT) Pf[i] = INF;
    }
    for (int i = t; i < CELLS; i += NT) mark[i] = 0;
    if (t < 3) flags[t] = 0;
    __syncthreads();

    float a = (t == 0) ? 0.0f : INF;        // (y0,   x0)
    float bv = INF;                          // (y0,   x0+1)
    float c = INF;                           // (y0+1, x0)
    float d = INF;                           // (y0+1, x0+1)
    sts2(sA, a, bv);
    sts2(sC, c, d);
    __syncthreads();

    // ---- chaotic min-plus relaxation: 2x2 register Gauss-Seidel per block,
    // Jacobi across blocks via packed smem. Every candidate is d[nb] + w in
    // RN: exact, monotone-decreasing, reference-attainable path sums; unique
    // fixed point == reference Dijkstra distances bitwise.
    int e = 0;
    for (;; e++) {
        const float sa = a, sb = bv, sc = c, sd = d;
#pragma unroll
        for (int k = 0; k < ESW; k++) {
            // 10 conflict-free LDS.64 (old values), front-batched
            const float2 Tm = lds2(aT);        // (x0-2, x0-1)
            const float2 Tc = lds2(aT + 8u);   // (x0,   x0+1)
            const float2 Tp = lds2(aT + 16u);  // (x0+2, x0+3)
            const float2 Bm = lds2(aB);
            const float2 Bc = lds2(aB + 8u);
            const float2 Bp = lds2(aB + 16u);
            const float2 La = lds2(aL);        // .y = l0
            const float2 Ra = lds2(aL + 16u);  // .x = r0
            const float2 Lc = lds2(aC);        // .y = l1
            const float2 Rc = lds2(aC + 16u);  // .x = r1

            // static (halo-only) min trees — off the GS chain
            const float mt = fminf(Tc.x, Tc.y);
            const float mb = fminf(Bc.x, Bc.y);
            const float ml = fminf(La.y, Lc.y);
            const float mr = fminf(Ra.x, Rc.x);
            const float hA = fminf(fminf(Tm.y, mt), ml);
            const float hB = fminf(fminf(Tp.x, mt), mr);
            const float hC = fminf(fminf(Bm.y, mb), ml);
            const float hD = fminf(fminf(Bp.x, mb), mr);

            // bidirectional Gauss-Seidel: a,b,c,d then c,b,a (short chains)
            a  = fminf(a,  fminf(hA, fminf(bv, fminf(c, d)))  + wa);
            bv = fminf(bv, fminf(hB, fminf(a,  fminf(c, d)))  + wb);
            c  = fminf(c,  fminf(hC, fminf(fminf(a, bv), d))  + wc);
            d  = fminf(d,  fminf(hD, fminf(fminf(a, bv), c))  + wd);
            c  = fminf(c,  fminf(hC, fminf(fminf(a, bv), d))  + wc);
            bv = fminf(bv, fminf(hB, fminf(a,  fminf(c, d)))  + wb);
            a  = fminf(a,  fminf(hA, fminf(bv, fminf(c, d)))  + wa);

            sts2(sA, a, bv);
            sts2(sC, c, d);
        }
        // registers monotone-decreasing: unchanged epoch everywhere => done
        if ((a != sa) | (bv != sb) | (c != sc) | (d != sd)) flags[e % 3] = 1;
        if (t == 0) flags[(e + 1) % 3] = 0;   // reset ordered by the barriers
        __syncthreads();
        if (!flags[e % 3]) break;             // uniform exit
    }

    // ---- predecessor = argmin over 8 neighbor distances (unique a.s.) ----
    {
        const float2 Tm = P[rt][tx],     Tc = P[rt][tx + 1], Tp = P[rt][tx + 2];
        const float2 Bm = P[rb][tx],     Bc = P[rb][tx + 1], Bp = P[rb][tx + 2];
        const float2 La = P[ra][tx],     Ra = P[ra][tx + 2];
        const float2 Lc = P[rc][tx],     Rc = P[rc][tx + 2];
        const float tl = Tm.y, tce = Tc.x, tco = Tc.y, tre = Tp.x;
        const float bl = Bm.y, bce = Bc.x, bco = Bc.y, bre = Bp.x;
        const float l0 = La.y, l1 = Lc.y, r0 = Ra.x, r1 = Rc.x;

        const int A = y0 * GRID_N + x0, B = A + 1, C = A + GRID_N, D = A + GRID_N + 1;

#define ARGMIN8(v1,i1,v2,i2,v3,i3,v4,i4,v5,i5,v6,i6,v7,i7,v8,i8, OUTCELL)      \
        {                                                                       \
            float bd = INF; int bi = 0;                                         \
            if (v1 < bd) { bd = v1; bi = i1; }                                  \
            if (v2 < bd) { bd = v2; bi = i2; }                                  \
            if (v3 < bd) { bd = v3; bi = i3; }                                  \
            if (v4 < bd) { bd = v4; bi = i4; }                                  \
            if (v5 < bd) { bd = v5; bi = i5; }                                  \
            if (v6 < bd) { bd = v6; bi = i6; }                                  \
            if (v7 < bd) { bd = v7; bi = i7; }                                  \
            if (v8 < bd) { bd = v8; bi = i8; }                                  \
            pred[OUTCELL] = (unsigned short)bi;                                 \
        }

        ARGMIN8(tl, A-33, tce, A-32, tco, A-31, l0, A-1, bv, A+1,
                l1, A+31, c, A+32, d, A+33, A)
        ARGMIN8(tce, B-33, tco, B-32, tre, B-31, a, B-1, r0, B+1,
                c, B+31, d, B+32, r1, B+33, B)
        ARGMIN8(l0, C-33, a, C-32, bv, C-31, l1, C-1, d, C+1,
                bl, C+31, bce, C+32, bco, C+33, C)
        ARGMIN8(a, D-33, bv, D-32, r0, D-31, c, D-1, r1, D+1,
                bce, D+31, bco, D+32, bre, D+33, D)
#undef ARGMIN8
    }
    __syncthreads();

    // ---- skip pointers: pred2/pred3/pred4 (parallel) ----
#pragma unroll
    for (int i = 0; i < 4; i++) {
        const int cell = t + i * NT;
        pred2[cell] = pred[pred[cell]];
    }
    __syncthreads();
#pragma unroll
    for (int i = 0; i < 4; i++) {
        const int cell = t + i * NT;
        const int q = pred2[cell];
        pred3[cell] = pred[q];
        pred4[cell] = pred2[q];
    }
    __syncthreads();

    // ---- backtrack from (31,31), 4 chain cells per iteration ----
    // pred chain strictly decreases dist, so it reaches cell 0.
    if (t == 0) {
        int cur = CELLS - 1;
        for (int i = 0; i < CELLS / 4 + 2; i++) {
            const int m1 = pred[cur];
            const int m2 = pred2[cur];
            const int m3 = pred3[cur];
            const int nx = pred4[cur];
            mark[cur] = 1;
            if (cur == 0) break;
            mark[m1] = 1;
            if (m1 == 0) break;
            mark[m2] = 1;
            if (m2 == 0) break;
            mark[m3] = 1;
            if (m3 == 0) break;
            cur = nx;
        }
    }
    __syncthreads();

    // ---- coalesced float2 output ----
    {
        float2* o2 = (float2*)(out + (size_t)b * CELLS);
        const int A = y0 * GRID_N + x0;
        o2[y0 * 16 + tx]       = make_float2(mark[A]      ? 1.0f : 0.0f,
                                             mark[A + 1]  ? 1.0f : 0.0f);
        o2[(y0 + 1) * 16 + tx] = make_float2(mark[A + 32] ? 1.0f : 0.0f,
                                             mark[A + 33] ? 1.0f : 0.0f);
    }
}

extern "C" void kernel_launch(void* const* d_in, const int* in_sizes, int n_in,
                              void* d_out, int out_size)
{
    const float* w = (const float*)d_in[0];
    float* out = (float*)d_out;
    int batches = in_sizes[0] / CELLS;     // 128
    dijkstra_grid_kernel<<<batches, NT>>>(w, out);
}